// round 5
// baseline (speedup 1.0000x reference)
#include <cuda_runtime.h>

#define HH 512
#define WW 512
#define NB 16
#define PLANE (HH*WW)
#define IMG (3*PLANE)
#define R 7
#define K 15
#define TX 128
#define TY 32
#define NTHR 512
#define HRW ((TX + 4*R)/2)   // 78  half-res region width
#define HRH ((TY + 4*R)/2)   // 30  half-res region height
#define DYW (TX + 2*R)       // 142 luma region width
#define DYH (TY + 2*R)       // 46  luma region height
#define HTY (TY/2)           // 16  half-res tile height
#define GX (WW/TX)           // 4
#define GY (HH/TY)           // 16
#define NBLK (GX*GY*NB)      // 1024

// dynamic smem layout (floats); dy rows i at [i+1], vy rows r at [r] (in-place)
#define OFF_DU   ((DYH+1)*DYW)                 // 6674
#define OFF_DV   (OFF_DU + (HRH+1)*HRW)       // +2418
#define OFF_RED  (OFF_DV + (HRH+1)*HRW)
#define SM_FLOATS (OFF_RED + 48)
#define SM_BYTES (SM_FLOATS * 4)

__device__ float g_acc[3];
__device__ unsigned int g_done;

template<bool SAFE>
__device__ __forceinline__ void phase1(
    const float* __restrict__ pin, const float* __restrict__ ptg,
    float (*s_dy)[DYW], float (*s_du)[HRW], float (*s_dv)[HRW],
    int tx0, int ty0, int tid)
{
    for (int idx = tid; idx < HRH * HRW; idx += NTHR) {
        int hr = idx / HRW;
        int hc = idx - hr * HRW;
        int fy = ty0 - 2 * R + 2 * hr;   // even
        int fx = tx0 - 2 * R + 2 * hc;   // even -> float2 aligned

        float2 ir0, ig0, ib0, tr0, tg0, tb0;
        float2 ir1, ig1, ib1, tr1, tg1, tb1;

        if (SAFE) {
            int o = fy * WW + fx;
            ir0 = *(const float2*)(pin + o);
            ig0 = *(const float2*)(pin + PLANE + o);
            ib0 = *(const float2*)(pin + 2*PLANE + o);
            tr0 = *(const float2*)(ptg + o);
            tg0 = *(const float2*)(ptg + PLANE + o);
            tb0 = *(const float2*)(ptg + 2*PLANE + o);
            o += WW;
            ir1 = *(const float2*)(pin + o);
            ig1 = *(const float2*)(pin + PLANE + o);
            ib1 = *(const float2*)(pin + 2*PLANE + o);
            tr1 = *(const float2*)(ptg + o);
            tg1 = *(const float2*)(ptg + PLANE + o);
            tb1 = *(const float2*)(ptg + 2*PLANE + o);
        } else {
            ir0 = {0.f,0.f}; ig0 = {0.f,0.f}; ib0 = {0.f,0.f};
            tr0 = {0.f,0.f}; tg0 = {0.f,0.f}; tb0 = {0.f,0.f};
            ir1 = {0.f,0.f}; ig1 = {0.f,0.f}; ib1 = {0.f,0.f};
            tr1 = {0.f,0.f}; tg1 = {0.f,0.f}; tb1 = {0.f,0.f};
            bool cx = (fx >= 0) & (fx < WW);
            if (cx & (fy >= 0) & (fy < HH)) {
                int o = fy * WW + fx;
                ir0 = *(const float2*)(pin + o);
                ig0 = *(const float2*)(pin + PLANE + o);
                ib0 = *(const float2*)(pin + 2*PLANE + o);
                tr0 = *(const float2*)(ptg + o);
                tg0 = *(const float2*)(ptg + PLANE + o);
                tb0 = *(const float2*)(ptg + 2*PLANE + o);
            }
            int fy1 = fy + 1;
            if (cx & (fy1 >= 0) & (fy1 < HH)) {
                int o = fy1 * WW + fx;
                ir1 = *(const float2*)(pin + o);
                ig1 = *(const float2*)(pin + PLANE + o);
                ib1 = *(const float2*)(pin + 2*PLANE + o);
                tr1 = *(const float2*)(ptg + o);
                tg1 = *(const float2*)(ptg + PLANE + o);
                tb1 = *(const float2*)(ptg + 2*PLANE + o);
            }
        }

        float dr00 = ir0.x - tr0.x, dr01 = ir0.y - tr0.y;
        float dr10 = ir1.x - tr1.x, dr11 = ir1.y - tr1.y;
        float dg00 = ig0.x - tg0.x, dg01 = ig0.y - tg0.y;
        float dg10 = ig1.x - tg1.x, dg11 = ig1.y - tg1.y;
        float db00 = ib0.x - tb0.x, db01 = ib0.y - tb0.y;
        float db10 = ib1.x - tb1.x, db11 = ib1.y - tb1.y;

        // pooled chroma diff (+128 offsets cancel in the difference)
        float Dr = dr00 + dr01 + dr10 + dr11;
        float Dg = dg00 + dg01 + dg10 + dg11;
        float Db = db00 + db01 + db10 + db11;
        s_du[hr + 1][hc] = 0.25f * (-0.169f * Dr - 0.331f * Dg + 0.5f  * Db);
        s_dv[hr + 1][hc] = 0.25f * ( 0.5f   * Dr - 0.46f  * Dg - 0.04f * Db);

        // luma diffs into the 46x142 luma region (stored at row+1)
        float dy00 = 0.299f*dr00 + 0.587f*dg00 + 0.114f*db00;
        float dy01 = 0.299f*dr01 + 0.587f*dg01 + 0.114f*db01;
        float dy10 = 0.299f*dr10 + 0.587f*dg10 + 0.114f*db10;
        float dy11 = 0.299f*dr11 + 0.587f*dg11 + 0.114f*db11;

        int dyr = 2 * hr - R;
        int dyc = 2 * hc - R;
        bool r0ok = (dyr >= 0) & (dyr < DYH);
        bool r1ok = (dyr + 1 >= 0) & (dyr + 1 < DYH);
        bool c0ok = (dyc >= 0) & (dyc < DYW);
        bool c1ok = (dyc + 1 >= 0) & (dyc + 1 < DYW);
        if (r0ok & c0ok) s_dy[dyr + 1][dyc]     = dy00;
        if (r0ok & c1ok) s_dy[dyr + 1][dyc + 1] = dy01;
        if (r1ok & c0ok) s_dy[dyr + 2][dyc]     = dy10;
        if (r1ok & c1ok) s_dy[dyr + 2][dyc + 1] = dy11;
    }
}

__global__ __launch_bounds__(NTHR) void yuv_loss_kernel(
    const float* __restrict__ inp, const float* __restrict__ tgt,
    float* __restrict__ out)
{
    extern __shared__ float sm[];
    float (*s_dy)[DYW] = (float (*)[DYW])(sm);
    float (*s_du)[HRW] = (float (*)[HRW])(sm + OFF_DU);
    float (*s_dv)[HRW] = (float (*)[HRW])(sm + OFF_DV);
    float* s_red = sm + OFF_RED;

    const int tid = threadIdx.x;
    const int n   = blockIdx.z;
    const int tx0 = blockIdx.x * TX;
    const int ty0 = blockIdx.y * TY;
    const float* pin = inp + (size_t)n * IMG;
    const float* ptg = tgt + (size_t)n * IMG;

    // ---- Phase 1: diff channels ----
    bool interior = (tx0 >= 2*R) & (tx0 + TX + 2*R <= WW) &
                    (ty0 >= 2*R) & (ty0 + TY + 2*R <= HH);
    if (interior) phase1<true >(pin, ptg, s_dy, s_du, s_dv, tx0, ty0, tid);
    else          phase1<false>(pin, ptg, s_dy, s_du, s_dv, tx0, ty0, tid);
    __syncthreads();

    // ---- Phase 2: vertical 15-tap running sums, in place over dead rows ----
    if (tid < DYW) {                     // 142 luma columns
        int c = tid;
        float s = 0.f;
        #pragma unroll
        for (int j = 0; j < K; j++) s += s_dy[j + 1][c];
        s_dy[0][c] = s;
        #pragma unroll 4
        for (int r = 1; r < TY; r++) {
            s += s_dy[r + K][c] - s_dy[r][c];   // + dy[r+14] - dy[r-1]
            s_dy[r][c] = s;                     // vy[r] over dead dy[r-1]
        }
    } else if (tid < DYW + 2 * HRW) {    // 2x78 chroma columns
        int t = tid - DYW;
        int ch = t / HRW;
        int c  = t - ch * HRW;
        float (*b)[HRW] = ch ? s_dv : s_du;
        float s = 0.f;
        #pragma unroll
        for (int j = 0; j < K; j++) s += b[j + 1][c];
        b[0][c] = s;
        #pragma unroll 5
        for (int r = 1; r < HTY; r++) {
            s += b[r + K][c] - b[r][c];
            b[r][c] = s;
        }
    }
    __syncthreads();

    // ---- Phase 3: horizontal 15-tap sliding sums, square, accumulate ----
    float accY = 0.f, accU = 0.f, accV = 0.f;
    {   // luma: 32 rows x 16 segments of 8 outputs = 512 threads
        int row = tid >> 4;
        int c0  = (tid & 15) * 8;
        float s = 0.f;
        #pragma unroll
        for (int j = 0; j < K; j++) s += s_dy[row][c0 + j];
        accY = s * s;
        #pragma unroll
        for (int i = 1; i < 8; i++) {
            s += s_dy[row][c0 + i + K - 1] - s_dy[row][c0 + i - 1];
            accY += s * s;
        }
    }
    {   // chroma: 2 ch x 16 rows x 16 segments of 4 outputs = 512 threads
        int ch  = tid >> 8;
        int rem = tid & 255;
        int row = rem >> 4;
        int c0  = (rem & 15) * 4;
        float (*v)[HRW] = ch ? s_dv : s_du;
        float s = 0.f;
        #pragma unroll
        for (int j = 0; j < K; j++) s += v[row][c0 + j];
        float a = s * s;
        #pragma unroll
        for (int i = 1; i < 4; i++) {
            s += v[row][c0 + i + K - 1] - v[row][c0 + i - 1];
            a += s * s;
        }
        if (ch) accV = a; else accU = a;
    }

    // ---- block reduction (16 warps) ----
    #pragma unroll
    for (int o = 16; o > 0; o >>= 1) {
        accY += __shfl_down_sync(0xffffffffu, accY, o);
        accU += __shfl_down_sync(0xffffffffu, accU, o);
        accV += __shfl_down_sync(0xffffffffu, accV, o);
    }
    int w = tid >> 5, l = tid & 31;
    if (l == 0) { s_red[w] = accY; s_red[16 + w] = accU; s_red[32 + w] = accV; }
    __syncthreads();
    if (tid == 0) {
        float sy = 0.f, su = 0.f, sv = 0.f;
        #pragma unroll
        for (int i = 0; i < 16; i++) { sy += s_red[i]; su += s_red[16+i]; sv += s_red[32+i]; }
        atomicAdd(&g_acc[0], sy);
        atomicAdd(&g_acc[1], su);
        atomicAdd(&g_acc[2], sv);
        __threadfence();
        unsigned int t = atomicAdd(&g_done, 1u);
        if (t == NBLK - 1) {
            const float invY = 1.0f / ((float)NB * HH * WW);
            const float invC = 1.0f / ((float)NB * (HH/2) * (WW/2));
            out[0] = g_acc[0] * invY + (g_acc[1] + g_acc[2]) * invC;
            g_acc[0] = 0.f; g_acc[1] = 0.f; g_acc[2] = 0.f;
            g_done = 0u;
        }
    }
}

extern "C" void kernel_launch(void* const* d_in, const int* in_sizes, int n_in,
                              void* d_out, int out_size)
{
    const float* inp = (const float*)d_in[0];
    const float* tgt = (const float*)d_in[1];
    float* out = (float*)d_out;

    static int configured = 0;
    if (!configured) {
        cudaFuncSetAttribute(yuv_loss_kernel,
                             cudaFuncAttributeMaxDynamicSharedMemorySize, SM_BYTES);
        configured = 1;
    }

    dim3 grid(GX, GY, NB);
    yuv_loss_kernel<<<grid, NTHR, SM_BYTES>>>(inp, tgt, out);
}

// round 6
// speedup vs baseline: 1.0638x; 1.0638x over previous
#include <cuda_runtime.h>

#define HH 512
#define WW 512
#define NB 16
#define PLANE (HH*WW)
#define IMG (3*PLANE)
#define R 7
#define K 15
#define TX 128
#define TY 32
#define NTHR 512
#define GX (WW/TX)           // 4
#define GY (HH/TY)           // 16
#define NBLK (GX*GY*NB)      // 1024

#define FRW 160              // full-res loaded region width (16B aligned)
#define FW4 (FRW/4)          // 40 float4 per row-pair item
#define HRH 30               // row-pair items (full-res rows ty0-14 .. ty0+45)
#define CRW 80               // chroma region width (cols cx0-8 .. cx0+71)
#define LROWS 54             // stored luma rows 1..53 (region rows 0..52) + vy rows 0..31
#define CROWS 31             // stored du rows 1..30 + vu rows 0..15
#define NITEM (HRH*FW4)      // 1200

// dynamic smem layout (floats)
#define OFF_DU   (LROWS*FRW)
#define OFF_DV   (OFF_DU + CROWS*CRW)
#define OFF_RED  (OFF_DV + CROWS*CRW)
#define SM_FLOATS (OFF_RED + 48)
#define SM_BYTES (SM_FLOATS * 4)

__device__ float g_acc[3];
__device__ unsigned int g_done;

__device__ __forceinline__ float4 f4sub(float4 a, float4 b) {
    return make_float4(a.x-b.x, a.y-b.y, a.z-b.z, a.w-b.w);
}

template<bool SAFE>
__device__ __forceinline__ void phase1(
    const float* __restrict__ pin, const float* __restrict__ ptg,
    float (*s_dy)[FRW], float (*s_du)[CRW], float (*s_dv)[CRW],
    int tx0, int ty0, int tid)
{
    const float4 Z = make_float4(0.f,0.f,0.f,0.f);
    for (int idx = tid; idx < NITEM; idx += NTHR) {
        int hr  = idx / FW4;
        int hc2 = idx - hr * FW4;
        int fy = ty0 - 2*R + 2*hr;        // even
        int fx = tx0 - 16 + 4*hc2;        // multiple of 4 -> 16B aligned

        int o0 = fy * WW + fx;
        int o1 = o0 + WW;

        bool p0 = true, p1 = true;
        if (!SAFE) {
            bool cx = (fx >= 0) & (fx < WW);
            p0 = cx & (fy >= 0)     & (fy < HH);
            p1 = cx & (fy + 1 >= 0) & (fy + 1 < HH);
        }

        // channel R
        float4 a0 = (SAFE || p0) ? *(const float4*)(pin + o0) : Z;
        float4 a1 = (SAFE || p1) ? *(const float4*)(pin + o1) : Z;
        float4 b0 = (SAFE || p0) ? *(const float4*)(ptg + o0) : Z;
        float4 b1 = (SAFE || p1) ? *(const float4*)(ptg + o1) : Z;
        float4 dr0 = f4sub(a0, b0), dr1 = f4sub(a1, b1);
        // channel G
        a0 = (SAFE || p0) ? *(const float4*)(pin + PLANE + o0) : Z;
        a1 = (SAFE || p1) ? *(const float4*)(pin + PLANE + o1) : Z;
        b0 = (SAFE || p0) ? *(const float4*)(ptg + PLANE + o0) : Z;
        b1 = (SAFE || p1) ? *(const float4*)(ptg + PLANE + o1) : Z;
        float4 dg0 = f4sub(a0, b0), dg1 = f4sub(a1, b1);
        // channel B
        a0 = (SAFE || p0) ? *(const float4*)(pin + 2*PLANE + o0) : Z;
        a1 = (SAFE || p1) ? *(const float4*)(pin + 2*PLANE + o1) : Z;
        b0 = (SAFE || p0) ? *(const float4*)(ptg + 2*PLANE + o0) : Z;
        b1 = (SAFE || p1) ? *(const float4*)(ptg + 2*PLANE + o1) : Z;
        float4 db0 = f4sub(a0, b0), db1 = f4sub(a1, b1);

        // luma diffs (8 pixels)
        float4 y0 = make_float4(
            0.299f*dr0.x + 0.587f*dg0.x + 0.114f*db0.x,
            0.299f*dr0.y + 0.587f*dg0.y + 0.114f*db0.y,
            0.299f*dr0.z + 0.587f*dg0.z + 0.114f*db0.z,
            0.299f*dr0.w + 0.587f*dg0.w + 0.114f*db0.w);
        float4 y1 = make_float4(
            0.299f*dr1.x + 0.587f*dg1.x + 0.114f*db1.x,
            0.299f*dr1.y + 0.587f*dg1.y + 0.114f*db1.y,
            0.299f*dr1.z + 0.587f*dg1.z + 0.114f*db1.z,
            0.299f*dr1.w + 0.587f*dg1.w + 0.114f*db1.w);

        // pooled 2x2 chroma diffs (2 quads; +128 offsets cancel)
        float DrA = dr0.x + dr0.y + dr1.x + dr1.y;
        float DrB = dr0.z + dr0.w + dr1.z + dr1.w;
        float DgA = dg0.x + dg0.y + dg1.x + dg1.y;
        float DgB = dg0.z + dg0.w + dg1.z + dg1.w;
        float DbA = db0.x + db0.y + db1.x + db1.y;
        float DbB = db0.z + db0.w + db1.z + db1.w;

        float2 du = make_float2(
            0.25f * (-0.169f*DrA - 0.331f*DgA + 0.5f *DbA),
            0.25f * (-0.169f*DrB - 0.331f*DgB + 0.5f *DbB));
        float2 dv = make_float2(
            0.25f * ( 0.5f  *DrA - 0.46f *DgA - 0.04f*DbA),
            0.25f * ( 0.5f  *DrB - 0.46f *DgB - 0.04f*DbB));

        // stores: luma rows stored at region_row+1, keep rows <= 53
        int lr0 = 2*hr + 1;
        if (lr0 <= LROWS - 1)  *(float4*)&s_dy[lr0][4*hc2] = y0;
        if (lr0 + 1 <= LROWS - 1) *(float4*)&s_dy[lr0 + 1][4*hc2] = y1;
        *(float2*)&s_du[hr + 1][2*hc2] = du;
        *(float2*)&s_dv[hr + 1][2*hc2] = dv;
    }
}

__global__ __launch_bounds__(NTHR, 3) void yuv_loss_kernel(
    const float* __restrict__ inp, const float* __restrict__ tgt,
    float* __restrict__ out)
{
    extern __shared__ float sm[];
    float (*s_dy)[FRW] = (float (*)[FRW])(sm);
    float (*s_du)[CRW] = (float (*)[CRW])(sm + OFF_DU);
    float (*s_dv)[CRW] = (float (*)[CRW])(sm + OFF_DV);
    float* s_red = sm + OFF_RED;

    const int tid = threadIdx.x;
    const int n   = blockIdx.z;
    const int tx0 = blockIdx.x * TX;
    const int ty0 = blockIdx.y * TY;
    const float* pin = inp + (size_t)n * IMG;
    const float* ptg = tgt + (size_t)n * IMG;

    // ---- Phase 1 ----
    bool interior = (tx0 >= 16) & (tx0 + TX + 16 <= WW) &
                    (ty0 >= 2*R) & (ty0 + TY + 2*R + 2 <= HH);
    if (interior) phase1<true >(pin, ptg, s_dy, s_du, s_dv, tx0, ty0, tid);
    else          phase1<false>(pin, ptg, s_dy, s_du, s_dv, tx0, ty0, tid);
    __syncthreads();

    // ---- Phase 2: vertical 15-tap running sums, in place ----
    // luma: dy region row i at stored row i+1; vy[r] -> row r (cols 9..150 used)
    if (tid < 142) {
        int c = tid + 9;
        float s = 0.f;
        #pragma unroll
        for (int j = 8; j <= 22; j++) s += s_dy[j][c];
        s_dy[0][c] = s;
        #pragma unroll 4
        for (int r = 1; r < TY; r++) {
            s += s_dy[r + 22][c] - s_dy[r + 7][c];
            s_dy[r][c] = s;
        }
    } else if (tid < 142 + 156) {     // chroma: 2 ch x 78 cols (cols 1..78)
        int t = tid - 142;
        int ch = (t >= 78);
        int c  = (ch ? t - 78 : t) + 1;
        float (*b)[CRW] = ch ? s_dv : s_du;
        float s = 0.f;
        #pragma unroll
        for (int j = 1; j <= 15; j++) s += b[j][c];
        b[0][c] = s;
        #pragma unroll 5
        for (int r = 1; r < TY/2; r++) {
            s += b[r + 15][c] - b[r][c];
            b[r][c] = s;
        }
    }
    __syncthreads();

    // ---- Phase 3: horizontal 15-tap sliding sums, square, accumulate ----
    float accY = 0.f, accU = 0.f, accV = 0.f;
    {   // luma: 32 rows x 16 segments of 8 outputs
        int row = tid >> 4;
        int c0  = (tid & 15) * 8 + 9;       // output x reads vy cols x+9..x+23
        float s = 0.f;
        #pragma unroll
        for (int j = 0; j < K; j++) s += s_dy[row][c0 + j];
        accY = s * s;
        #pragma unroll
        for (int i = 1; i < 8; i++) {
            s += s_dy[row][c0 + i + K - 1] - s_dy[row][c0 + i - 1];
            accY += s * s;
        }
    }
    {   // chroma: 2 ch x 16 rows x 16 segments of 4 outputs
        int ch  = tid >> 8;
        int rem = tid & 255;
        int row = rem >> 4;
        int c0  = (rem & 15) * 4 + 1;       // output xc reads vu cols xc+1..xc+15
        float (*v)[CRW] = ch ? s_dv : s_du;
        float s = 0.f;
        #pragma unroll
        for (int j = 0; j < K; j++) s += v[row][c0 + j];
        float a = s * s;
        #pragma unroll
        for (int i = 1; i < 4; i++) {
            s += v[row][c0 + i + K - 1] - v[row][c0 + i - 1];
            a += s * s;
        }
        if (ch) accV = a; else accU = a;
    }

    // ---- block reduction (16 warps) ----
    #pragma unroll
    for (int o = 16; o > 0; o >>= 1) {
        accY += __shfl_down_sync(0xffffffffu, accY, o);
        accU += __shfl_down_sync(0xffffffffu, accU, o);
        accV += __shfl_down_sync(0xffffffffu, accV, o);
    }
    int w = tid >> 5, l = tid & 31;
    if (l == 0) { s_red[w] = accY; s_red[16 + w] = accU; s_red[32 + w] = accV; }
    __syncthreads();
    if (tid == 0) {
        float sy = 0.f, su = 0.f, sv = 0.f;
        #pragma unroll
        for (int i = 0; i < 16; i++) { sy += s_red[i]; su += s_red[16+i]; sv += s_red[32+i]; }
        atomicAdd(&g_acc[0], sy);
        atomicAdd(&g_acc[1], su);
        atomicAdd(&g_acc[2], sv);
        __threadfence();
        unsigned int t = atomicAdd(&g_done, 1u);
        if (t == NBLK - 1) {
            const float invY = 1.0f / ((float)NB * HH * WW);
            const float invC = 1.0f / ((float)NB * (HH/2) * (WW/2));
            out[0] = g_acc[0] * invY + (g_acc[1] + g_acc[2]) * invC;
            g_acc[0] = 0.f; g_acc[1] = 0.f; g_acc[2] = 0.f;
            g_done = 0u;
        }
    }
}

extern "C" void kernel_launch(void* const* d_in, const int* in_sizes, int n_in,
                              void* d_out, int out_size)
{
    const float* inp = (const float*)d_in[0];
    const float* tgt = (const float*)d_in[1];
    float* out = (float*)d_out;

    static int configured = 0;
    if (!configured) {
        cudaFuncSetAttribute(yuv_loss_kernel,
                             cudaFuncAttributeMaxDynamicSharedMemorySize, SM_BYTES);
        configured = 1;
    }

    dim3 grid(GX, GY, NB);
    yuv_loss_kernel<<<grid, NTHR, SM_BYTES>>>(inp, tgt, out);
}